// round 5
// baseline (speedup 1.0000x reference)
#include <cuda_runtime.h>
#include <cuda_fp16.h>

#define C 128
#define MAX_USERS   50000
#define MAX_ENT     50000
#define MAX_NODES  100000
#define MAX_E     1000000
#define DEGS 100000          // deg segment stride
#define OFFS 100008          // off/cursor segment stride
#define PS   132             // partials segment stride

// ---------------- scratch (allocation-free: __device__ globals) ----------------
__device__ __half g_hNodeA [(size_t)MAX_NODES * C];
__device__ __half g_hNodeB [(size_t)MAX_NODES * C];
__device__ __half g_hEntB  [(size_t)MAX_ENT   * C];
__device__ __half g_hEntM  [(size_t)MAX_ENT   * C];
__device__ __half g_hQ     [(size_t)MAX_NODES * C];
__device__ __half g_hK     [(size_t)MAX_NODES * C];
__device__ __half g_WT     [2 * C * C];               // [mat][n][k] fp16 (W transposed)
__device__ int    g_srt_ent[MAX_E];
__device__ int    g_srt_x  [MAX_E];
__device__ int2   g_srt_i  [MAX_E];
__device__ float2 g_exps   [MAX_E];
__device__ float  g_aug    [MAX_E];
__device__ int    g_deg3   [3 * DEGS];
__device__ int    g_off3   [3 * OFFS];
__device__ int    g_cur3   [3 * OFFS];
__device__ int    g_part3  [3 * PS];

// ---------------- half pack/unpack ----------------
__device__ __forceinline__ uint2 pack4(float a, float b, float c, float d) {
    __half2 h0 = __floats2half2_rn(a, b);
    __half2 h1 = __floats2half2_rn(c, d);
    uint2 r; r.x = *(unsigned*)&h0; r.y = *(unsigned*)&h1; return r;
}
__device__ __forceinline__ void unpack8(uint4 v, float* f) {
    __half2 h0 = *(__half2*)&v.x, h1 = *(__half2*)&v.y;
    __half2 h2 = *(__half2*)&v.z, h3 = *(__half2*)&v.w;
    float2 a = __half22float2(h0), b = __half22float2(h1);
    float2 c = __half22float2(h2), d = __half22float2(h3);
    f[0] = a.x; f[1] = a.y; f[2] = b.x; f[3] = b.y;
    f[4] = c.x; f[5] = c.y; f[6] = d.x; f[7] = d.y;
}
__device__ __forceinline__ uint4 pack8(const float* f) {
    __half2 h0 = __floats2half2_rn(f[0], f[1]);
    __half2 h1 = __floats2half2_rn(f[2], f[3]);
    __half2 h2 = __floats2half2_rn(f[4], f[5]);
    __half2 h3 = __floats2half2_rn(f[6], f[7]);
    uint4 r;
    r.x = *(unsigned*)&h0; r.y = *(unsigned*)&h1;
    r.z = *(unsigned*)&h2; r.w = *(unsigned*)&h3;
    return r;
}

// ================= fp32 (user|ent) -> fp16 concat =================
__global__ __launch_bounds__(256) void conv2(const float* __restrict__ a,
                                             const float* __restrict__ b,
                                             size_t n4a, size_t n4, __half* __restrict__ dst)
{
    size_t i = (size_t)blockIdx.x * 256 + threadIdx.x;
    if (i >= n4) return;
    float4 v = (i < n4a) ? __ldg((const float4*)a + i) : __ldg((const float4*)b + (i - n4a));
    ((uint2*)dst)[i] = pack4(v.x, v.y, v.z, v.w);
}

// ================= W fp32 [k][n] -> fp16 transposed [mat][n][k] =================
__global__ __launch_bounds__(256) void wt_conv(const float* __restrict__ WQ,
                                               const float* __restrict__ WK,
                                               __half* __restrict__ WT)
{
    int i = blockIdx.x * 256 + threadIdx.x;
    if (i >= 2 * C * C) return;
    int mat = i >> 14, r = i & 16383;
    int k = r >> 7, n = r & 127;
    float v = mat ? __ldg(WK + r) : __ldg(WQ + r);
    WT[mat * C * C + n * C + k] = __float2half_rn(v);
}

// ================= CSR build (batched over the 3 graphs) =================
__global__ __launch_bounds__(256) void hist3(
    const int* __restrict__ h_e, int E1,
    const int* __restrict__ h_x, int E2,
    const int* __restrict__ h_u, int E3, int* __restrict__ deg3)
{
    int i = blockIdx.x * 256 + threadIdx.x;
    if (i < E1) { atomicAdd(deg3 + __ldg(h_e + i), 1); return; }
    i -= E1;
    if (i < E2) { atomicAdd(deg3 + DEGS + __ldg(h_x + i), 1); return; }
    i -= E2;
    if (i < E3) atomicAdd(deg3 + 2 * DEGS + __ldg(h_u + i), 1);
}

__global__ __launch_bounds__(1024) void scan_block3(const int* __restrict__ deg3,
                                                    int* __restrict__ off3, int* __restrict__ part3,
                                                    int n0, int n1, int n2)
{
    __shared__ int ws[32];
    int y = blockIdx.y;
    int n = (y == 0) ? n0 : ((y == 1) ? n1 : n2);
    const int* deg = deg3 + y * DEGS;
    int* off = off3 + y * OFFS;
    int* part = part3 + y * PS;
    int t = threadIdx.x;
    int gid = blockIdx.x * 1024 + t;
    int v = (gid < n) ? deg[gid] : 0;
    int x = v;
#pragma unroll
    for (int d = 1; d < 32; d <<= 1) {
        int yv = __shfl_up_sync(0xffffffffu, x, d);
        if ((t & 31) >= d) x += yv;
    }
    if ((t & 31) == 31) ws[t >> 5] = x;
    __syncthreads();
    if (t < 32) {
        int s = ws[t];
#pragma unroll
        for (int d = 1; d < 32; d <<= 1) {
            int yv = __shfl_up_sync(0xffffffffu, s, d);
            if (t >= d) s += yv;
        }
        ws[t] = s;
    }
    __syncthreads();
    int excl = x - v + ((t >= 32) ? ws[(t >> 5) - 1] : 0);
    if (gid < n) off[gid] = excl;
    if (t == 1023) part[blockIdx.x] = excl + v;
}

__global__ void scan_part3(int* __restrict__ part3)
{
    int t = threadIdx.x;            // 96 threads
    int w = t >> 5, lane = t & 31;
    int* part = part3 + w * PS;
    int v[4];
#pragma unroll
    for (int i = 0; i < 4; i++) v[i] = part[lane * 4 + i];
    int loc = v[0] + v[1] + v[2] + v[3];
    int x = loc;
#pragma unroll
    for (int d = 1; d < 32; d <<= 1) {
        int y = __shfl_up_sync(0xffffffffu, x, d);
        if (lane >= d) x += y;
    }
    int excl = x - loc;
#pragma unroll
    for (int i = 0; i < 4; i++) { part[lane * 4 + i] = excl; excl += v[i]; }
}

__global__ __launch_bounds__(256) void add_offs3(int* __restrict__ off3,
                                                 const int* __restrict__ part3,
                                                 int n0, int n1, int n2)
{
    int y = blockIdx.y;
    int n = (y == 0) ? n0 : ((y == 1) ? n1 : n2);
    int* off = off3 + y * OFFS;
    const int* part = part3 + y * PS;
    int i = blockIdx.x * 256 + threadIdx.x;
    if (i < n) off[i] += part[i >> 10];
    else if (i == n) off[i] = part[(n + 1023) >> 10];
}

__global__ __launch_bounds__(256) void scat3(
    const int* __restrict__ eh, const int* __restrict__ et, const int* __restrict__ ety, int E1,
    const int* __restrict__ xh, const int* __restrict__ xt, int E2,
    const int* __restrict__ ir, const int* __restrict__ ic, const float* __restrict__ iv, int E3,
    int* __restrict__ cur3, int* __restrict__ srt_e, int* __restrict__ srt_x, int2* __restrict__ srt_i)
{
    int i = blockIdx.x * 256 + threadIdx.x;
    if (i < E1) {
        int p = atomicAdd(cur3 + __ldg(eh + i), 1);
        srt_e[p] = __ldg(et + i) | ((__ldg(ety + i) - 1) << 16);
        return;
    }
    i -= E1;
    if (i < E2) {
        int p = atomicAdd(cur3 + OFFS + __ldg(xh + i), 1);
        srt_x[p] = __ldg(xt + i);
        return;
    }
    i -= E2;
    if (i < E3) {
        int p = atomicAdd(cur3 + 2 * OFFS + __ldg(ir + i), 1);
        srt_i[p] = make_int2(__ldg(ic + i), __float_as_int(__ldg(iv + i)));
    }
}

// ================= Q/K projection via HMMA =================
#define SB_H (2 * 128 * 136)
#define SA_H (64 * 136)
__global__ __launch_bounds__(256) void qk_mma(
    const __half* __restrict__ node, const __half* __restrict__ WT,
    __half* __restrict__ Q, __half* __restrict__ K, int n)
{
    extern __shared__ __half sh[];
    __half* sB = sh;            // [mat*128 + n][136]
    __half* sA = sh + SB_H;     // [row][136]
    int t = threadIdx.x;
    int row0 = blockIdx.x * 64;

    for (int i = t; i < 4096; i += 256) {
        uint4 v = __ldg((const uint4*)WT + i);
        int nn = i >> 4, k8 = (i & 15) << 3;
        *(uint4*)(sB + nn * 136 + k8) = v;
    }
    for (int i = t; i < 1024; i += 256) {
        int r = i >> 4, k8 = (i & 15) << 3;
        int gr = row0 + r;
        uint4 v = make_uint4(0u, 0u, 0u, 0u);
        if (gr < n) v = __ldg((const uint4*)(node + (size_t)gr * C) + (i & 15));
        *(uint4*)(sA + r * 136 + k8) = v;
    }
    __syncthreads();

    int lane = t & 31, wid = t >> 5;
    int rg = wid & 3, cg = wid >> 2;
    int arow = rg * 16 + (lane >> 2);
    int kq = (lane & 3) * 2;

#pragma unroll
    for (int mat = 0; mat < 2; mat++) {
        float acc[8][4];
#pragma unroll
        for (int nt = 0; nt < 8; nt++)
#pragma unroll
            for (int c = 0; c < 4; c++) acc[nt][c] = 0.f;

#pragma unroll
        for (int kk = 0; kk < 128; kk += 16) {
            unsigned a0 = *(unsigned*)(sA + arow * 136 + kk + kq);
            unsigned a1 = *(unsigned*)(sA + (arow + 8) * 136 + kk + kq);
            unsigned a2 = *(unsigned*)(sA + arow * 136 + kk + kq + 8);
            unsigned a3 = *(unsigned*)(sA + (arow + 8) * 136 + kk + kq + 8);
#pragma unroll
            for (int nt = 0; nt < 8; nt++) {
                int nn = mat * 128 + cg * 64 + nt * 8 + (lane >> 2);
                unsigned b0 = *(unsigned*)(sB + nn * 136 + kk + kq);
                unsigned b1 = *(unsigned*)(sB + nn * 136 + kk + kq + 8);
                asm volatile(
                    "mma.sync.aligned.m16n8k16.row.col.f32.f16.f16.f32 "
                    "{%0,%1,%2,%3}, {%4,%5,%6,%7}, {%8,%9}, {%0,%1,%2,%3};"
                    : "+f"(acc[nt][0]), "+f"(acc[nt][1]), "+f"(acc[nt][2]), "+f"(acc[nt][3])
                    : "r"(a0), "r"(a1), "r"(a2), "r"(a3), "r"(b0), "r"(b1));
            }
        }

        __half* outb = mat ? K : Q;
        int grow = row0 + rg * 16 + (lane >> 2);
#pragma unroll
        for (int nt = 0; nt < 8; nt++) {
            int col = cg * 64 + nt * 8 + (lane & 3) * 2;
            if (grow < n) {
                __half2 h = __floats2half2_rn(acc[nt][0], acc[nt][1]);
                *(__half2*)(outb + (size_t)grow * C + col) = h;
            }
            if (grow + 8 < n) {
                __half2 h = __floats2half2_rn(acc[nt][2], acc[nt][3]);
                *(__half2*)(outb + (size_t)(grow + 8) * C + col) = h;
            }
        }
    }
}

// ================= fused attention (CSR): 2 edges per warp-step =================
__global__ __launch_bounds__(256) void attn_csr(
    const int* __restrict__ off, const int* __restrict__ srt,
    const __half* __restrict__ Q, const __half* __restrict__ K,
    float2* __restrict__ exps, float* __restrict__ aug, int n)
{
    int gw = (blockIdx.x * 256 + threadIdx.x) >> 5, lane = threadIdx.x & 31;
    if (gw >= n) return;
    int base = off[gw], end = off[gw + 1];
    if (base == end) return;
    int half = lane >> 4, hl = lane & 15;
    float q8[8];
    unpack8(__ldg((const uint4*)(Q + (size_t)gw * C) + hl), q8);
    float zacc = 0.f;
    for (int e0 = base; e0 < end; e0 += 32) {
        int cnt = min(32, end - e0);
        int meta = (lane < cnt) ? __ldg(srt + e0 + lane) : 0;
        float my0 = 0.f, my1 = 0.f;
        for (int j = 0; j < cnt; j += 2) {
            int jb = min(j + 1, cnt - 1);
            int m0 = __shfl_sync(0xffffffffu, meta, j);
            int m1 = __shfl_sync(0xffffffffu, meta, jb);
            int m = half ? m1 : m0;
            bool valid = (half == 0) | (j + 1 < cnt);
            float k8[8];
            unpack8(__ldg((const uint4*)(K + (size_t)m * C) + hl), k8);
            float p = q8[0]*k8[0] + q8[1]*k8[1] + q8[2]*k8[2] + q8[3]*k8[3]
                    + q8[4]*k8[4] + q8[5]*k8[5] + q8[6]*k8[6] + q8[7]*k8[7];
            p += __shfl_xor_sync(0xffffffffu, p, 4);
            p += __shfl_xor_sync(0xffffffffu, p, 2);
            p += __shfl_xor_sync(0xffffffffu, p, 1);
            float ex = valid ? __expf(p * 0.125f) : 0.f;
            zacc += ex;
            float eA0 = __shfl_sync(0xffffffffu, ex, 0);
            float eA1 = __shfl_sync(0xffffffffu, ex, 8);
            float eB0 = __shfl_sync(0xffffffffu, ex, 16);
            float eB1 = __shfl_sync(0xffffffffu, ex, 24);
            if (lane == j)      { my0 = eA0; my1 = eA1; }
            if (lane == j + 1)  { my0 = eB0; my1 = eB1; }
        }
        if (lane < cnt) exps[e0 + lane] = make_float2(my0, my1);
    }
    // z per head: head0 partials in lanes 0-7 & 16-23, head1 in 8-15 & 24-31
    float z0 = __shfl_sync(0xffffffffu, zacc, 0) + __shfl_sync(0xffffffffu, zacc, 16);
    float z1 = __shfl_sync(0xffffffffu, zacc, 8) + __shfl_sync(0xffffffffu, zacc, 24);
    float iz0 = 0.5f / z0, iz1 = 0.5f / z1;
    for (int e0 = base; e0 < end; e0 += 32) {
        int cnt = min(32, end - e0);
        if (lane < cnt) {
            float2 ex = exps[e0 + lane];
            aug[e0 + lane] = ex.x * iz0 + ex.y * iz1;
        }
    }
}

// ================= entity KG aggregation (2 edges/step, fused mean+norm+res) ========
__global__ __launch_bounds__(256) void ent_agg_csr(
    const int* __restrict__ off, const int* __restrict__ srt,
    const __half* __restrict__ src, const float* __restrict__ wgt,
    __half* __restrict__ mean_out, __half* __restrict__ cur_out,
    float* __restrict__ res, const float* __restrict__ res_init, int n)
{
    __shared__ float sW[15 * C];
    for (int i = threadIdx.x; i < 15 * C; i += 256) sW[i] = wgt[i];
    __syncthreads();
    int gw = (blockIdx.x * 256 + threadIdx.x) >> 5, lane = threadIdx.x & 31;
    if (gw >= n) return;
    int half = lane >> 4, hl = lane & 15;
    int base = off[gw], end = off[gw + 1];
    float acc[8];
#pragma unroll
    for (int i = 0; i < 8; i++) acc[i] = 0.f;

    for (int e0 = base; e0 < end; e0 += 32) {
        int cnt = min(32, end - e0);
        int meta = (lane < cnt) ? __ldg(srt + e0 + lane) : 0;
#pragma unroll 4
        for (int j = 0; j < cnt; j += 2) {
            int jb = min(j + 1, cnt - 1);
            int m0 = __shfl_sync(0xffffffffu, meta, j);
            int m1 = __shfl_sync(0xffffffffu, meta, jb);
            int m = half ? m1 : m0;
            float vf = ((half == 0) | (j + 1 < cnt)) ? 1.f : 0.f;
            float f[8];
            unpack8(__ldg((const uint4*)(src + (size_t)(m & 0xFFFF) * C) + hl), f);
            const float* wrow = sW + (((unsigned)m) >> 16) * C + hl * 8;
            float4 w0 = *(const float4*)(wrow);
            float4 w1 = *(const float4*)(wrow + 4);
            acc[0] += vf * f[0] * w0.x; acc[1] += vf * f[1] * w0.y;
            acc[2] += vf * f[2] * w0.z; acc[3] += vf * f[3] * w0.w;
            acc[4] += vf * f[4] * w1.x; acc[5] += vf * f[5] * w1.y;
            acc[6] += vf * f[6] * w1.z; acc[7] += vf * f[7] * w1.w;
        }
    }
#pragma unroll
    for (int i = 0; i < 8; i++) acc[i] += __shfl_xor_sync(0xffffffffu, acc[i], 16);

    float inv = 1.0f / fmaxf((float)(end - base), 1.0f);
    float m8[8];
#pragma unroll
    for (int i = 0; i < 8; i++) m8[i] = acc[i] * inv;
    float ss = 0.f;
#pragma unroll
    for (int i = 0; i < 8; i++) ss += m8[i] * m8[i];
    ss += __shfl_xor_sync(0xffffffffu, ss, 8);
    ss += __shfl_xor_sync(0xffffffffu, ss, 4);
    ss += __shfl_xor_sync(0xffffffffu, ss, 2);
    ss += __shfl_xor_sync(0xffffffffu, ss, 1);
    float ni = 1.0f / fmaxf(sqrtf(ss), 1e-12f);
    if (half == 0) {
        ((uint4*)(mean_out + (size_t)gw * C))[hl] = pack8(m8);
        float o8[8];
#pragma unroll
        for (int i = 0; i < 8; i++) o8[i] = m8[i] * ni;
        if (cur_out) ((uint4*)(cur_out + (size_t)gw * C))[hl] = pack8(o8);
        const float4* rin = (const float4*)(res_init + (size_t)gw * C) + hl * 2;
        float4 r0 = __ldg(rin), r1 = __ldg(rin + 1);
        r0.x += o8[0]; r0.y += o8[1]; r0.z += o8[2]; r0.w += o8[3];
        r1.x += o8[4]; r1.y += o8[5]; r1.z += o8[6]; r1.w += o8[7];
        float4* ro = (float4*)(res + (size_t)gw * C) + hl * 2;
        ro[0] = r0; ro[1] = r1;
    }
}

// ================= preference-graph aggregation (2 edges/step, fused norm+res) ======
__global__ __launch_bounds__(256) void node_agg_csr(
    const int* __restrict__ off, const int* __restrict__ srt,
    const float* __restrict__ aug, const __half* __restrict__ src,
    __half* __restrict__ cur_out, float* __restrict__ res,
    const float* __restrict__ ri0, const float* __restrict__ ri1, int split, int n)
{
    int gw = (blockIdx.x * 256 + threadIdx.x) >> 5, lane = threadIdx.x & 31;
    if (gw >= n) return;
    int half = lane >> 4, hl = lane & 15;
    int base = off[gw], end = off[gw + 1];
    float acc[8];
#pragma unroll
    for (int i = 0; i < 8; i++) acc[i] = 0.f;

    for (int e0 = base; e0 < end; e0 += 32) {
        int cnt = min(32, end - e0);
        int meta = 0; float av = 0.f;
        if (lane < cnt) { meta = __ldg(srt + e0 + lane); av = __ldg(aug + e0 + lane); }
#pragma unroll 4
        for (int j = 0; j < cnt; j += 2) {
            int jb = min(j + 1, cnt - 1);
            int m0 = __shfl_sync(0xffffffffu, meta, j);
            int m1 = __shfl_sync(0xffffffffu, meta, jb);
            float a0 = __shfl_sync(0xffffffffu, av, j);
            float a1 = __shfl_sync(0xffffffffu, av, jb);
            int m = half ? m1 : m0;
            float a = half ? a1 : a0;
            if (!((half == 0) | (j + 1 < cnt))) a = 0.f;
            float f[8];
            unpack8(__ldg((const uint4*)(src + (size_t)m * C) + hl), f);
#pragma unroll
            for (int i = 0; i < 8; i++) acc[i] += f[i] * a;
        }
    }
#pragma unroll
    for (int i = 0; i < 8; i++) acc[i] += __shfl_xor_sync(0xffffffffu, acc[i], 16);

    float ss = 0.f;
#pragma unroll
    for (int i = 0; i < 8; i++) ss += acc[i] * acc[i];
    ss += __shfl_xor_sync(0xffffffffu, ss, 8);
    ss += __shfl_xor_sync(0xffffffffu, ss, 4);
    ss += __shfl_xor_sync(0xffffffffu, ss, 2);
    ss += __shfl_xor_sync(0xffffffffu, ss, 1);
    float ni = 1.0f / fmaxf(sqrtf(ss), 1e-12f);
    if (half == 0) {
        float o8[8];
#pragma unroll
        for (int i = 0; i < 8; i++) o8[i] = acc[i] * ni;
        if (cur_out) ((uint4*)(cur_out + (size_t)gw * C))[hl] = pack8(o8);
        const float* rib = (gw < split) ? ri0 + (size_t)gw * C : ri1 + (size_t)(gw - split) * C;
        const float4* rin = (const float4*)rib + hl * 2;
        float4 r0 = __ldg(rin), r1 = __ldg(rin + 1);
        r0.x += o8[0]; r0.y += o8[1]; r0.z += o8[2]; r0.w += o8[3];
        r1.x += o8[4]; r1.y += o8[5]; r1.z += o8[6]; r1.w += o8[7];
        float4* ro = (float4*)(res + (size_t)gw * C) + hl * 2;
        ro[0] = r0; ro[1] = r1;
    }
}

// ================= interact-mat aggregation (2 edges/step, fused norm+res) ==========
__global__ __launch_bounds__(256) void user_agg_csr(
    const int* __restrict__ off, const int2* __restrict__ srt,
    const __half* __restrict__ src, float* __restrict__ res,
    const float* __restrict__ res_init, int n)
{
    int gw = (blockIdx.x * 256 + threadIdx.x) >> 5, lane = threadIdx.x & 31;
    if (gw >= n) return;
    int half = lane >> 4, hl = lane & 15;
    int base = off[gw], end = off[gw + 1];
    float acc[8];
#pragma unroll
    for (int i = 0; i < 8; i++) acc[i] = 0.f;

    for (int e0 = base; e0 < end; e0 += 32) {
        int cnt = min(32, end - e0);
        int mc = 0; float mv = 0.f;
        if (lane < cnt) { int2 p = __ldg(srt + e0 + lane); mc = p.x; mv = __int_as_float(p.y); }
#pragma unroll 4
        for (int j = 0; j < cnt; j += 2) {
            int jb = min(j + 1, cnt - 1);
            int m0 = __shfl_sync(0xffffffffu, mc, j);
            int m1 = __shfl_sync(0xffffffffu, mc, jb);
            float a0 = __shfl_sync(0xffffffffu, mv, j);
            float a1 = __shfl_sync(0xffffffffu, mv, jb);
            int m = half ? m1 : m0;
            float a = half ? a1 : a0;
            if (!((half == 0) | (j + 1 < cnt))) a = 0.f;
            float f[8];
            unpack8(__ldg((const uint4*)(src + (size_t)m * C) + hl), f);
#pragma unroll
            for (int i = 0; i < 8; i++) acc[i] += f[i] * a;
        }
    }
#pragma unroll
    for (int i = 0; i < 8; i++) acc[i] += __shfl_xor_sync(0xffffffffu, acc[i], 16);

    float ss = 0.f;
#pragma unroll
    for (int i = 0; i < 8; i++) ss += acc[i] * acc[i];
    ss += __shfl_xor_sync(0xffffffffu, ss, 8);
    ss += __shfl_xor_sync(0xffffffffu, ss, 4);
    ss += __shfl_xor_sync(0xffffffffu, ss, 2);
    ss += __shfl_xor_sync(0xffffffffu, ss, 1);
    float ni = 1.0f / fmaxf(sqrtf(ss), 1e-12f);
    if (half == 0) {
        float o8[8];
#pragma unroll
        for (int i = 0; i < 8; i++) o8[i] = acc[i] * ni;
        const float4* rin = (const float4*)(res_init + (size_t)gw * C) + hl * 2;
        float4 r0 = __ldg(rin), r1 = __ldg(rin + 1);
        r0.x += o8[0]; r0.y += o8[1]; r0.z += o8[2]; r0.w += o8[3];
        r1.x += o8[4]; r1.y += o8[5]; r1.z += o8[6]; r1.w += o8[7];
        float4* ro = (float4*)(res + (size_t)gw * C) + hl * 2;
        ro[0] = r0; ro[1] = r1;
    }
}

// ================= host launcher =================
extern "C" void kernel_launch(void* const* d_in, const int* in_sizes, int n_in,
                              void* d_out, int out_size)
{
    const float* user   = (const float*)d_in[0];
    const float* ent    = (const float*)d_in[1];
    const int*   eidx   = (const int*)  d_in[2];
    const int*   etype  = (const int*)  d_in[3];
    const int*   exidx  = (const int*)  d_in[4];
    const int*   irows  = (const int*)  d_in[6];
    const int*   icols  = (const int*)  d_in[7];
    const float* ivals  = (const float*)d_in[8];
    const float* weight = (const float*)d_in[9];
    const float* WQ     = (const float*)d_in[11];
    const float* WK     = (const float*)d_in[12];

    int n_users = in_sizes[0] / C;
    int n_ent   = in_sizes[1] / C;
    int n_nodes = n_users + n_ent;
    int E   = in_sizes[3];
    int EX  = in_sizes[5];
    int NNZ = in_sizes[6];

    size_t UB = (size_t)n_users * C;
    size_t EB = (size_t)n_ent * C;

    float *augp;
    __half *hNodeA, *hNodeB, *hEntB, *hEntM, *hQ, *hK, *WT;
    float2* exps;
    int *srt_e, *srt_x, *off3, *cur3, *deg3, *part3;
    int2* srt_i;
    cudaGetSymbolAddress((void**)&hNodeA, g_hNodeA);
    cudaGetSymbolAddress((void**)&hNodeB, g_hNodeB);
    cudaGetSymbolAddress((void**)&hEntB,  g_hEntB);
    cudaGetSymbolAddress((void**)&hEntM,  g_hEntM);
    cudaGetSymbolAddress((void**)&hQ,     g_hQ);
    cudaGetSymbolAddress((void**)&hK,     g_hK);
    cudaGetSymbolAddress((void**)&WT,     g_WT);
    cudaGetSymbolAddress((void**)&augp,   g_aug);
    cudaGetSymbolAddress((void**)&exps,   g_exps);
    cudaGetSymbolAddress((void**)&srt_e,  g_srt_ent);
    cudaGetSymbolAddress((void**)&srt_x,  g_srt_x);
    cudaGetSymbolAddress((void**)&srt_i,  g_srt_i);
    cudaGetSymbolAddress((void**)&off3,   g_off3);
    cudaGetSymbolAddress((void**)&cur3,   g_cur3);
    cudaGetSymbolAddress((void**)&deg3,   g_deg3);
    cudaGetSymbolAddress((void**)&part3,  g_part3);

    int* off_e = off3;
    int* off_n = off3 + OFFS;
    int* off_u = off3 + 2 * OFFS;

    float* out = (float*)d_out;
    float* user_res = out;              // [n_users, C]
    float* ent_res  = out + UB;         // [n_ent, C]
    float* node_res = out + UB + EB;    // [n_nodes, C]

    const int* eh = eidx;          const int* et = eidx + E;
    const int* xh = exidx;         const int* xt = exidx + EX;

    {
        size_t n4 = (size_t)n_nodes * 32;
        conv2<<<(unsigned)((n4 + 255) / 256), 256>>>(user, ent, UB / 4, n4, hNodeA);
    }
    wt_conv<<<(2 * C * C + 255) / 256, 256>>>(WQ, WK, WT);

    // ---- batched CSR build for the 3 graphs ----
    cudaMemsetAsync(deg3, 0, 3 * DEGS * 4);
    {
        int tot = E + EX + NNZ;
        hist3<<<(tot + 255) / 256, 256>>>(eh, E, xh, EX, irows, NNZ, deg3);
    }
    {
        dim3 g((n_nodes + 1023) >> 10, 3);
        scan_block3<<<g, 1024>>>(deg3, off3, part3, n_ent, n_nodes, n_users);
        scan_part3<<<1, 96>>>(part3);
        dim3 g2((n_nodes + 256) / 256 + 1, 3);
        add_offs3<<<g2, 256>>>(off3, part3, n_ent, n_nodes, n_users);
    }
    cudaMemcpyAsync(cur3, off3, 3 * OFFS * 4, cudaMemcpyDeviceToDevice);
    {
        int tot = E + EX + NNZ;
        scat3<<<(tot + 255) / 256, 256>>>(eh, et, etype, E, xh, xt, EX,
                                          irows, icols, ivals, NNZ,
                                          cur3, srt_e, srt_x, srt_i);
    }

    // ---- attention weights (once; reused both hops) ----
    {
        int smem = (SB_H + SA_H) * 2;
        cudaFuncSetAttribute(qk_mma, cudaFuncAttributeMaxDynamicSharedMemorySize, smem);
        qk_mma<<<(n_nodes + 63) / 64, 256, smem>>>(hNodeA, WT, hQ, hK, n_nodes);
    }
    attn_csr<<<(n_nodes * 32 + 255) / 256, 256>>>(off_n, srt_x, hQ, hK, exps, augp, n_nodes);

    // ---- hop 1 ----
    ent_agg_csr<<<(n_ent * 32 + 255) / 256, 256>>>(
        off_e, srt_e, hNodeA + UB, weight, hEntM, hEntB, ent_res, ent, n_ent);
    user_agg_csr<<<(n_users * 32 + 255) / 256, 256>>>(
        off_u, srt_i, hEntM, user_res, user, n_users);
    node_agg_csr<<<(n_nodes * 32 + 255) / 256, 256>>>(
        off_n, srt_x, augp, hNodeA, hNodeB, node_res, user, ent, n_users, n_nodes);

    // ---- hop 2 ----
    ent_agg_csr<<<(n_ent * 32 + 255) / 256, 256>>>(
        off_e, srt_e, hEntB, weight, hEntM, (__half*)0, ent_res, ent_res, n_ent);
    user_agg_csr<<<(n_users * 32 + 255) / 256, 256>>>(
        off_u, srt_i, hEntM, user_res, user_res, n_users);
    node_agg_csr<<<(n_nodes * 32 + 255) / 256, 256>>>(
        off_n, srt_x, augp, hNodeB, (__half*)0, node_res, node_res, node_res, n_nodes, n_nodes);
}